// round 6
// baseline (speedup 1.0000x reference)
#include <cuda_runtime.h>
#include <math.h>

#define NPIX 8192
#define DD 256
#define SS 16
#define MLPH 1024

// ---------- scratch (device globals; no runtime allocation) ----------
__device__ float g_off[NPIX * 32];
__device__ float g_cmb[DD * 1024];           // Cmb[dd][a*256+d]
__device__ float g_bqw[1024];
__device__ float g_qw[(size_t)NPIX * 1024];
__device__ float g_ctx[(size_t)NPIX * 1024];
__device__ float g_attn[(size_t)NPIX * DD];
__device__ float g_o[(size_t)NPIX * DD];
__device__ float g_x[(size_t)NPIX * DD];
__device__ float g_h[(size_t)NPIX * MLPH];
__device__ float g_m[(size_t)NPIX * DD];

__device__ __forceinline__ float gelu_tanh(float v) {
    float c = 0.7978845608028654f * (v + 0.044715f * v * v * v);
    return 0.5f * v * (1.0f + tanhf(c));
}

// ---------- 1) offsets: off[p][o] = sigmoid-map(hs[p,:] @ W_off[:,o] + b_off[o]) ----------
__global__ __launch_bounds__(256) void offs_kernel(
    const float* __restrict__ hs, const float* __restrict__ W_off,
    const float* __restrict__ b_off)
{
    int w = threadIdx.x >> 5, lane = threadIdx.x & 31;
    int p = blockIdx.x * 8 + w;
    const float* hp = hs + (size_t)p * DD;
    float acc = 0.f;
    for (int db = 0; db < DD; db += 32) {
        float hv = hp[db + lane];
        #pragma unroll
        for (int j = 0; j < 32; ++j) {
            float h = __shfl_sync(0xffffffffu, hv, j);
            acc += h * W_off[(db + j) * 32 + lane];
        }
    }
    float z = acc + b_off[lane];
    g_off[p * 32 + lane] = 60.0f / (1.0f + expf(-z)) - 30.0f;
}

// ---------- 2) Cmb[dd][a*256+d] = sum_e Wq[dd][a*64+e] * 0.125*Wk[d][a*64+e] ----------
__global__ __launch_bounds__(256) void prep_cmb(
    const float* __restrict__ Wq, const float* __restrict__ Wk)
{
    int j = blockIdx.x;           // j = a*256 + d
    int a = j >> 8, d = j & 255;
    __shared__ float wk_s[64];
    int t = threadIdx.x;
    if (t < 64) wk_s[t] = 0.125f * Wk[d * DD + a * 64 + t];
    __syncthreads();
    const float* wq = Wq + t * DD + a * 64;
    float acc = 0.f;
    #pragma unroll 16
    for (int e = 0; e < 64; ++e) acc += wq[e] * wk_s[e];
    g_cmb[t * 1024 + j] = acc;
}

__global__ void prep_bqw(const float* __restrict__ bq, const float* __restrict__ Wk) {
    int j = blockIdx.x * 256 + threadIdx.x;
    int a = j >> 8, d = j & 255;
    float acc = 0.f;
    #pragma unroll 16
    for (int e = 0; e < 64; ++e)
        acc += bq[a * 64 + e] * 0.125f * Wk[d * DD + a * 64 + e];
    g_bqw[j] = acc;
}

// ---------- generic 64x64-tile GEMM: C = A@B + bias (MODE 1: gelu) ----------
// Ab = A + mb*64*lda + nb*a_koff   (a_koff=256 gives block-diagonal head GEMM)
template <int MODE>
__global__ __launch_bounds__(256) void gemm64(
    const float* __restrict__ A, int lda, int a_koff,
    const float* __restrict__ B, int ldb,
    const float* __restrict__ bias,
    float* __restrict__ C, int ldc, int K)
{
    __shared__ __align__(16) float As[16][68];
    __shared__ __align__(16) float Bs[16][68];
    int t = threadIdx.x;
    int mb = blockIdx.x, nb = blockIdx.y;
    const float* Ab = A + (size_t)(mb * 64) * lda + nb * a_koff;
    const float* Bb = B + nb * 64;

    int am = t >> 2, ak = (t & 3) * 4;    // A loader: row am, k ak..ak+3
    int bk = t >> 4, bn = (t & 15) * 4;   // B loader: row bk, col bn..bn+3
    int ty = t >> 4, tx = t & 15;
    int m0 = ty * 4, n0 = tx * 4;

    float acc[4][4] = {};
    float4 av = *(const float4*)&Ab[(size_t)am * lda + ak];
    float4 bv = *(const float4*)&Bb[(size_t)bk * ldb + bn];

    for (int k0 = 0; k0 < K; k0 += 16) {
        __syncthreads();
        As[ak + 0][am] = av.x; As[ak + 1][am] = av.y;
        As[ak + 2][am] = av.z; As[ak + 3][am] = av.w;
        *(float4*)&Bs[bk][bn] = bv;
        __syncthreads();
        if (k0 + 16 < K) {
            av = *(const float4*)&Ab[(size_t)am * lda + k0 + 16 + ak];
            bv = *(const float4*)&Bb[(size_t)(k0 + 16 + bk) * ldb + bn];
        }
        #pragma unroll
        for (int k = 0; k < 16; ++k) {
            float4 a4 = *(const float4*)&As[k][m0];
            float4 b4 = *(const float4*)&Bs[k][n0];
            acc[0][0] += a4.x * b4.x; acc[0][1] += a4.x * b4.y;
            acc[0][2] += a4.x * b4.z; acc[0][3] += a4.x * b4.w;
            acc[1][0] += a4.y * b4.x; acc[1][1] += a4.y * b4.y;
            acc[1][2] += a4.y * b4.z; acc[1][3] += a4.y * b4.w;
            acc[2][0] += a4.z * b4.x; acc[2][1] += a4.z * b4.y;
            acc[2][2] += a4.z * b4.z; acc[2][3] += a4.z * b4.w;
            acc[3][0] += a4.w * b4.x; acc[3][1] += a4.w * b4.y;
            acc[3][2] += a4.w * b4.z; acc[3][3] += a4.w * b4.w;
        }
    }

    float4 bb = *(const float4*)&bias[nb * 64 + n0];
    #pragma unroll
    for (int i = 0; i < 4; ++i) {
        float4 cv;
        cv.x = acc[i][0] + bb.x; cv.y = acc[i][1] + bb.y;
        cv.z = acc[i][2] + bb.z; cv.w = acc[i][3] + bb.w;
        if (MODE == 1) {
            cv.x = gelu_tanh(cv.x); cv.y = gelu_tanh(cv.y);
            cv.z = gelu_tanh(cv.z); cv.w = gelu_tanh(cv.w);
        }
        *(float4*)&C[(size_t)(mb * 64 + m0 + i) * ldc + nb * 64 + n0] = cv;
    }
}

// ---------- gather + scores + softmax + ctx (one pixel per 256-thread block) ----------
__global__ __launch_bounds__(256) void gather_attn(
    const float* __restrict__ emb,
    const float* __restrict__ W_kvp, const float* __restrict__ b_kvp)
{
    __shared__ __align__(16) float kvs[SS][264];
    __shared__ __align__(16) float qws[1024];
    __shared__ float offs[32];
    __shared__ float scs[64];
    __shared__ float ps[64];

    int t = threadIdx.x, p = blockIdx.x;
    int n = p >> 12, hh = (p >> 6) & 63, ww = p & 63;

    if (t < 32) offs[t] = g_off[p * 32 + t];
    *(float4*)&qws[t * 4] = *(const float4*)&g_qw[(size_t)p * 1024 + t * 4];
    __syncthreads();

    // gather (thread = feature d)
    {
        float wk0 = W_kvp[t], wk1 = W_kvp[DD + t], bkv = b_kvp[t];
        const float* base = emb + (size_t)n * 64 * 64 * DD + t;
        float fh = (float)hh, fw = (float)ww;
        #pragma unroll 4
        for (int s = 0; s < SS; ++s) {
            float oy = offs[2 * s], ox = offs[2 * s + 1];
            float y = fminf(fmaxf(fh + oy, 0.f), 63.f);
            float x = fminf(fmaxf(fw + ox, 0.f), 63.f);
            float y0f = floorf(y), x0f = floorf(x);
            float wy = y - y0f, wx = x - x0f;
            int y0 = (int)y0f, x0 = (int)x0f;
            int y1 = min(y0 + 1, 63), x1 = min(x0 + 1, 63);
            float v00 = base[(y0 * 64 + x0) * DD];
            float v01 = base[(y0 * 64 + x1) * DD];
            float v10 = base[(y1 * 64 + x0) * DD];
            float v11 = base[(y1 * 64 + x1) * DD];
            float val = (1.f - wy) * ((1.f - wx) * v00 + wx * v01)
                      +        wy  * ((1.f - wx) * v10 + wx * v11);
            kvs[s][t] = val + oy * wk0 + ox * wk1 + bkv;
        }
    }
    __syncthreads();

    // scores: thread = (as = a*16+s, c = d-quarter); 4-lane split reduction
    {
        int as = t >> 2, c = t & 3;
        int a = as >> 4, s = as & 15;
        const float* kp = &kvs[s][c * 64];
        const float* qp = &qws[a * 256 + c * 64];
        float acc = 0.f;
        #pragma unroll 8
        for (int i = 0; i < 64; i += 4) {
            float4 k4 = *(const float4*)&kp[i];
            float4 q4 = *(const float4*)&qp[i];
            acc += k4.x * q4.x + k4.y * q4.y + k4.z * q4.z + k4.w * q4.w;
        }
        acc += __shfl_xor_sync(0xffffffffu, acc, 1);
        acc += __shfl_xor_sync(0xffffffffu, acc, 2);
        if (c == 0) scs[as] = acc;
    }
    __syncthreads();

    if (t < 64) {
        float sc = scs[t];
        float mx = sc;
        #pragma unroll
        for (int m = 8; m >= 1; m >>= 1)
            mx = fmaxf(mx, __shfl_xor_sync(0xffffffffu, mx, m, 16));
        float ex = expf(sc - mx);
        float sum = ex;
        #pragma unroll
        for (int m = 8; m >= 1; m >>= 1)
            sum += __shfl_xor_sync(0xffffffffu, sum, m, 16);
        ps[t] = ex / sum;
    }
    __syncthreads();

    // ctx[a][d] = sum_s p[a,s]*kv[s][d]
    {
        float kcol[SS];
        #pragma unroll
        for (int s = 0; s < SS; ++s) kcol[s] = kvs[s][t];
        #pragma unroll
        for (int a = 0; a < 4; ++a) {
            float acc = 0.f;
            #pragma unroll
            for (int s = 0; s < SS; ++s) acc += ps[a * 16 + s] * kcol[s];
            g_ctx[(size_t)p * 1024 + a * 256 + t] = acc;
        }
    }
}

// ---------- layernorm: out = LN(g + res)*s + b ----------
__global__ __launch_bounds__(256) void ln_kernel(
    const float* __restrict__ g, const float* __restrict__ res,
    const float* __restrict__ s, const float* __restrict__ b,
    float* __restrict__ out)
{
    __shared__ float red[16];
    int r = blockIdx.x, t = threadIdx.x;
    float v = g[(size_t)r * DD + t] + res[(size_t)r * DD + t];
    float s1 = v, s2 = v * v;
    #pragma unroll
    for (int m = 16; m >= 1; m >>= 1) {
        s1 += __shfl_xor_sync(0xffffffffu, s1, m);
        s2 += __shfl_xor_sync(0xffffffffu, s2, m);
    }
    int wid = t >> 5, lid = t & 31;
    if (lid == 0) { red[wid] = s1; red[8 + wid] = s2; }
    __syncthreads();
    float m1 = 0.f, m2 = 0.f;
    #pragma unroll
    for (int w = 0; w < 8; ++w) { m1 += red[w]; m2 += red[8 + w]; }
    m1 *= (1.f / 256.f);
    m2 = m2 * (1.f / 256.f) - m1 * m1;
    out[(size_t)r * DD + t] = (v - m1) * rsqrtf(m2 + 1e-6f) * s[t] + b[t];
}

// ---------- launcher ----------
extern "C" void kernel_launch(void* const* d_in, const int* in_sizes, int n_in,
                              void* d_out, int out_size)
{
    const float* hs    = (const float*)d_in[0];
    const float* emb   = (const float*)d_in[1];
    const float* W_off = (const float*)d_in[2];
    const float* b_off = (const float*)d_in[3];
    const float* W_kvp = (const float*)d_in[4];
    const float* b_kvp = (const float*)d_in[5];
    const float* Wq = (const float*)d_in[6];  const float* bq = (const float*)d_in[7];
    const float* Wk = (const float*)d_in[8];  // bk cancels in softmax
    const float* Wv = (const float*)d_in[10]; const float* bv = (const float*)d_in[11];
    const float* Wo = (const float*)d_in[12]; const float* bo = (const float*)d_in[13];
    const float* ln1s = (const float*)d_in[14]; const float* ln1b = (const float*)d_in[15];
    const float *ln2s, *ln2b, *W1, *b1, *W2, *b2;
    if (in_sizes[16] == 256) {
        ln2s = (const float*)d_in[16]; ln2b = (const float*)d_in[17];
        W1   = (const float*)d_in[18]; b1   = (const float*)d_in[19];
        W2   = (const float*)d_in[20]; b2   = (const float*)d_in[21];
    } else {
        W1   = (const float*)d_in[16]; b1   = (const float*)d_in[17];
        W2   = (const float*)d_in[18]; b2   = (const float*)d_in[19];
        ln2s = (const float*)d_in[20]; ln2b = (const float*)d_in[21];
    }

    float *p_cmb, *p_bqw, *p_qw, *p_ctx, *p_attn, *p_o, *p_x, *p_h, *p_m;
    cudaGetSymbolAddress((void**)&p_cmb, g_cmb);
    cudaGetSymbolAddress((void**)&p_bqw, g_bqw);
    cudaGetSymbolAddress((void**)&p_qw, g_qw);
    cudaGetSymbolAddress((void**)&p_ctx, g_ctx);
    cudaGetSymbolAddress((void**)&p_attn, g_attn);
    cudaGetSymbolAddress((void**)&p_o, g_o);
    cudaGetSymbolAddress((void**)&p_x, g_x);
    cudaGetSymbolAddress((void**)&p_h, g_h);
    cudaGetSymbolAddress((void**)&p_m, g_m);

    // 1) offsets
    offs_kernel<<<NPIX / 8, 256>>>(hs, W_off, b_off);
    // 2) combined score weights
    prep_cmb<<<1024, 256>>>(Wq, Wk);
    prep_bqw<<<4, 256>>>(bq, Wk);
    // 3) qw = hs @ Cmb + bqw                         [8192 x 1024]
    gemm64<0><<<dim3(128, 16), 256>>>(hs, DD, 0, p_cmb, 1024, p_bqw, p_qw, 1024, DD);
    // 4) gather + softmax + ctx                      [8192 x 1024]
    gather_attn<<<NPIX, 256>>>(emb, W_kvp, b_kvp);
    // 5) attn = ctx (block-diag) @ Wv + bv           [8192 x 256]
    gemm64<0><<<dim3(128, 4), 256>>>(p_ctx, 1024, 256, Wv, DD, bv, p_attn, DD, DD);
    // 6) o = attn @ Wo + bo                          [8192 x 256]
    gemm64<0><<<dim3(128, 4), 256>>>(p_attn, DD, 0, Wo, DD, bo, p_o, DD, DD);
    // 7) x = LN1(o + hs)
    ln_kernel<<<NPIX, 256>>>(p_o, hs, ln1s, ln1b, p_x);
    // 8) h = gelu(x @ W1 + b1)                       [8192 x 1024]
    gemm64<1><<<dim3(128, 16), 256>>>(p_x, DD, 0, W1, MLPH, b1, p_h, MLPH, DD);
    // 9) m = h @ W2 + b2                             [8192 x 256]
    gemm64<0><<<dim3(128, 4), 256>>>(p_h, MLPH, 0, W2, DD, b2, p_m, DD, MLPH);
    // 10) out = LN2(m + x)
    ln_kernel<<<NPIX, 256>>>(p_m, p_x, ln2s, ln2b, (float*)d_out);
}

// round 7
// speedup vs baseline: 1.1372x; 1.1372x over previous
#include <cuda_runtime.h>
#include <math.h>

#define NPIX 8192
#define DD 256
#define SS 16
#define MLPH 1024

// ---------- scratch (device globals; no runtime allocation) ----------
__device__ float g_off[NPIX * 32];
__device__ float g_cmb[DD * 1024];           // Cmb[dd][a*256+d]
__device__ float g_bqw[1024];
__device__ float g_qw[(size_t)NPIX * 1024];
__device__ float g_ctx[(size_t)NPIX * 1024];
__device__ float g_attn[(size_t)NPIX * DD];
__device__ float g_o[(size_t)NPIX * DD];
__device__ float g_x[(size_t)NPIX * DD];
__device__ float g_h[(size_t)NPIX * MLPH];
__device__ float g_m[(size_t)NPIX * DD];

__device__ __forceinline__ float gelu_tanh(float v) {
    float c = 0.7978845608028654f * (v + 0.044715f * v * v * v);
    return 0.5f * v * (1.0f + tanhf(c));
}

// ---------- 1) offsets ----------
__global__ __launch_bounds__(256) void offs_kernel(
    const float* __restrict__ hs, const float* __restrict__ W_off,
    const float* __restrict__ b_off)
{
    int w = threadIdx.x >> 5, lane = threadIdx.x & 31;
    int p = blockIdx.x * 8 + w;
    const float* hp = hs + (size_t)p * DD;
    float acc = 0.f;
    for (int db = 0; db < DD; db += 32) {
        float hv = hp[db + lane];
        #pragma unroll
        for (int j = 0; j < 32; ++j) {
            float h = __shfl_sync(0xffffffffu, hv, j);
            acc += h * W_off[(db + j) * 32 + lane];
        }
    }
    float z = acc + b_off[lane];
    g_off[p * 32 + lane] = 60.0f / (1.0f + expf(-z)) - 30.0f;
}

// ---------- 2) Cmb[dd][a*256+d] = sum_e Wq[dd][a*64+e] * 0.125*Wk[d][a*64+e] ----------
__global__ __launch_bounds__(256) void prep_cmb(
    const float* __restrict__ Wq, const float* __restrict__ Wk)
{
    int j = blockIdx.x;           // j = a*256 + d
    int a = j >> 8, d = j & 255;
    __shared__ float wk_s[64];
    int t = threadIdx.x;
    if (t < 64) wk_s[t] = 0.125f * Wk[d * DD + a * 64 + t];
    __syncthreads();
    const float* wq = Wq + t * DD + a * 64;
    float acc = 0.f;
    #pragma unroll 16
    for (int e = 0; e < 64; ++e) acc += wq[e] * wk_s[e];
    g_cmb[t * 1024 + j] = acc;
}

__global__ void prep_bqw(const float* __restrict__ bq, const float* __restrict__ Wk) {
    int j = blockIdx.x * 256 + threadIdx.x;
    int a = j >> 8, d = j & 255;
    float acc = 0.f;
    #pragma unroll 16
    for (int e = 0; e < 64; ++e)
        acc += bq[a * 64 + e] * 0.125f * Wk[d * DD + a * 64 + e];
    g_bqw[j] = acc;
}

// ---------- big-tile GEMM: MT=128 x NTILE, 8x(NTILE/16) micro-tile ----------
// C[M x N] = A@B + bias ; Ab = A + mb*128*lda + nb*a_koff (a_koff=256 -> block-diag)
template <int NTILE, int MODE>
__global__ __launch_bounds__(256) void gemm_big(
    const float* __restrict__ A, int lda, int a_koff,
    const float* __restrict__ B, int ldb,
    const float* __restrict__ bias,
    float* __restrict__ C, int ldc, int K)
{
    constexpr int NR = NTILE / 16;     // 8 or 4
    __shared__ __align__(16) float As[16][132];
    __shared__ __align__(16) float Bs[16][NTILE + 4];

    int t = threadIdx.x;
    int mb = blockIdx.x, nb = blockIdx.y;
    const float* Ab = A + (size_t)(mb * 128) * lda + nb * a_koff;
    const float* Bb = B + nb * NTILE;

    // loaders
    int am = t >> 2, ak = (t & 3) * 4;                     // A rows am, am+64
    int bk, bn;
    if (NTILE == 128) { bk = t >> 5; bn = (t & 31) * 4; }  // B rows bk, bk+8
    else              { bk = t >> 4; bn = (t & 15) * 4; }  // single

    // compute thread map
    int tx = t & 15, ty = t >> 4;
    int m0 = ty * 4, n0 = tx * 4;

    float acc[8][NR];
    #pragma unroll
    for (int i = 0; i < 8; ++i)
        #pragma unroll
        for (int j = 0; j < NR; ++j) acc[i][j] = 0.f;

    float4 a0p = *(const float4*)&Ab[(size_t)am * lda + ak];
    float4 a1p = *(const float4*)&Ab[(size_t)(am + 64) * lda + ak];
    float4 b0p = *(const float4*)&Bb[(size_t)bk * ldb + bn];
    float4 b1p;
    if (NTILE == 128) b1p = *(const float4*)&Bb[(size_t)(bk + 8) * ldb + bn];

    for (int k0 = 0; k0 < K; k0 += 16) {
        __syncthreads();
        As[ak + 0][am] = a0p.x; As[ak + 1][am] = a0p.y;
        As[ak + 2][am] = a0p.z; As[ak + 3][am] = a0p.w;
        As[ak + 0][am + 64] = a1p.x; As[ak + 1][am + 64] = a1p.y;
        As[ak + 2][am + 64] = a1p.z; As[ak + 3][am + 64] = a1p.w;
        *(float4*)&Bs[bk][bn] = b0p;
        if (NTILE == 128) *(float4*)&Bs[bk + 8][bn] = b1p;
        __syncthreads();

        if (k0 + 16 < K) {
            a0p = *(const float4*)&Ab[(size_t)am * lda + k0 + 16 + ak];
            a1p = *(const float4*)&Ab[(size_t)(am + 64) * lda + k0 + 16 + ak];
            b0p = *(const float4*)&Bb[(size_t)(k0 + 16 + bk) * ldb + bn];
            if (NTILE == 128) b1p = *(const float4*)&Bb[(size_t)(k0 + 24 + bk) * ldb + bn];
        }

        #pragma unroll
        for (int k = 0; k < 16; ++k) {
            float4 av0 = *(const float4*)&As[k][m0];
            float4 av1 = *(const float4*)&As[k][m0 + 64];
            float ar[8] = {av0.x, av0.y, av0.z, av0.w, av1.x, av1.y, av1.z, av1.w};
            float br[NR];
            float4 bv0 = *(const float4*)&Bs[k][n0];
            br[0] = bv0.x; br[1] = bv0.y; br[2] = bv0.z; br[3] = bv0.w;
            if (NTILE == 128) {
                float4 bv1 = *(const float4*)&Bs[k][n0 + 64];
                br[4] = bv1.x; br[5] = bv1.y; br[6] = bv1.z; br[7] = bv1.w;
            }
            #pragma unroll
            for (int i = 0; i < 8; ++i)
                #pragma unroll
                for (int j = 0; j < NR; ++j)
                    acc[i][j] += ar[i] * br[j];
        }
    }

    // epilogue
    float4 bb0 = *(const float4*)&bias[nb * NTILE + n0];
    float4 bb1;
    if (NTILE == 128) bb1 = *(const float4*)&bias[nb * NTILE + n0 + 64];
    #pragma unroll
    for (int i = 0; i < 8; ++i) {
        int row = mb * 128 + (i < 4 ? m0 + i : m0 + 60 + i);
        float4 c0;
        c0.x = acc[i][0] + bb0.x; c0.y = acc[i][1] + bb0.y;
        c0.z = acc[i][2] + bb0.z; c0.w = acc[i][3] + bb0.w;
        if (MODE == 1) {
            c0.x = gelu_tanh(c0.x); c0.y = gelu_tanh(c0.y);
            c0.z = gelu_tanh(c0.z); c0.w = gelu_tanh(c0.w);
        }
        *(float4*)&C[(size_t)row * ldc + nb * NTILE + n0] = c0;
        if (NTILE == 128) {
            float4 c1;
            c1.x = acc[i][4] + bb1.x; c1.y = acc[i][5] + bb1.y;
            c1.z = acc[i][6] + bb1.z; c1.w = acc[i][7] + bb1.w;
            if (MODE == 1) {
                c1.x = gelu_tanh(c1.x); c1.y = gelu_tanh(c1.y);
                c1.z = gelu_tanh(c1.z); c1.w = gelu_tanh(c1.w);
            }
            *(float4*)&C[(size_t)row * ldc + nb * NTILE + n0 + 64] = c1;
        }
    }
}

// ---------- gather + scores + softmax + ctx ----------
__global__ __launch_bounds__(256) void gather_attn(
    const float* __restrict__ emb,
    const float* __restrict__ W_kvp, const float* __restrict__ b_kvp)
{
    __shared__ __align__(16) float kvs[SS][264];
    __shared__ __align__(16) float qws[1024];
    __shared__ float offs[32];
    __shared__ float scs[64];
    __shared__ float ps[64];

    int t = threadIdx.x, p = blockIdx.x;
    int n = p >> 12, hh = (p >> 6) & 63, ww = p & 63;

    if (t < 32) offs[t] = g_off[p * 32 + t];
    *(float4*)&qws[t * 4] = *(const float4*)&g_qw[(size_t)p * 1024 + t * 4];
    __syncthreads();

    {
        float wk0 = W_kvp[t], wk1 = W_kvp[DD + t], bkv = b_kvp[t];
        const float* base = emb + (size_t)n * 64 * 64 * DD + t;
        float fh = (float)hh, fw = (float)ww;
        #pragma unroll 4
        for (int s = 0; s < SS; ++s) {
            float oy = offs[2 * s], ox = offs[2 * s + 1];
            float y = fminf(fmaxf(fh + oy, 0.f), 63.f);
            float x = fminf(fmaxf(fw + ox, 0.f), 63.f);
            float y0f = floorf(y), x0f = floorf(x);
            float wy = y - y0f, wx = x - x0f;
            int y0 = (int)y0f, x0 = (int)x0f;
            int y1 = min(y0 + 1, 63), x1 = min(x0 + 1, 63);
            float v00 = base[(y0 * 64 + x0) * DD];
            float v01 = base[(y0 * 64 + x1) * DD];
            float v10 = base[(y1 * 64 + x0) * DD];
            float v11 = base[(y1 * 64 + x1) * DD];
            float val = (1.f - wy) * ((1.f - wx) * v00 + wx * v01)
                      +        wy  * ((1.f - wx) * v10 + wx * v11);
            kvs[s][t] = val + oy * wk0 + ox * wk1 + bkv;
        }
    }
    __syncthreads();

    {
        int as = t >> 2, c = t & 3;
        int a = as >> 4, s = as & 15;
        const float* kp = &kvs[s][c * 64];
        const float* qp = &qws[a * 256 + c * 64];
        float acc = 0.f;
        #pragma unroll 8
        for (int i = 0; i < 64; i += 4) {
            float4 k4 = *(const float4*)&kp[i];
            float4 q4 = *(const float4*)&qp[i];
            acc += k4.x * q4.x + k4.y * q4.y + k4.z * q4.z + k4.w * q4.w;
        }
        acc += __shfl_xor_sync(0xffffffffu, acc, 1);
        acc += __shfl_xor_sync(0xffffffffu, acc, 2);
        if (c == 0) scs[as] = acc;
    }
    __syncthreads();

    if (t < 64) {
        float sc = scs[t];
        float mx = sc;
        #pragma unroll
        for (int m = 8; m >= 1; m >>= 1)
            mx = fmaxf(mx, __shfl_xor_sync(0xffffffffu, mx, m, 16));
        float ex = expf(sc - mx);
        float sum = ex;
        #pragma unroll
        for (int m = 8; m >= 1; m >>= 1)
            sum += __shfl_xor_sync(0xffffffffu, sum, m, 16);
        ps[t] = ex / sum;
    }
    __syncthreads();

    {
        float kcol[SS];
        #pragma unroll
        for (int s = 0; s < SS; ++s) kcol[s] = kvs[s][t];
        #pragma unroll
        for (int a = 0; a < 4; ++a) {
            float acc = 0.f;
            #pragma unroll
            for (int s = 0; s < SS; ++s) acc += ps[a * 16 + s] * kcol[s];
            g_ctx[(size_t)p * 1024 + a * 256 + t] = acc;
        }
    }
}

// ---------- layernorm ----------
__global__ __launch_bounds__(256) void ln_kernel(
    const float* __restrict__ g, const float* __restrict__ res,
    const float* __restrict__ s, const float* __restrict__ b,
    float* __restrict__ out)
{
    __shared__ float red[16];
    int r = blockIdx.x, t = threadIdx.x;
    float v = g[(size_t)r * DD + t] + res[(size_t)r * DD + t];
    float s1 = v, s2 = v * v;
    #pragma unroll
    for (int m = 16; m >= 1; m >>= 1) {
        s1 += __shfl_xor_sync(0xffffffffu, s1, m);
        s2 += __shfl_xor_sync(0xffffffffu, s2, m);
    }
    int wid = t >> 5, lid = t & 31;
    if (lid == 0) { red[wid] = s1; red[8 + wid] = s2; }
    __syncthreads();
    float m1 = 0.f, m2 = 0.f;
    #pragma unroll
    for (int w = 0; w < 8; ++w) { m1 += red[w]; m2 += red[8 + w]; }
    m1 *= (1.f / 256.f);
    m2 = m2 * (1.f / 256.f) - m1 * m1;
    out[(size_t)r * DD + t] = (v - m1) * rsqrtf(m2 + 1e-6f) * s[t] + b[t];
}

// ---------- launcher ----------
extern "C" void kernel_launch(void* const* d_in, const int* in_sizes, int n_in,
                              void* d_out, int out_size)
{
    const float* hs    = (const float*)d_in[0];
    const float* emb   = (const float*)d_in[1];
    const float* W_off = (const float*)d_in[2];
    const float* b_off = (const float*)d_in[3];
    const float* W_kvp = (const float*)d_in[4];
    const float* b_kvp = (const float*)d_in[5];
    const float* Wq = (const float*)d_in[6];  const float* bq = (const float*)d_in[7];
    const float* Wk = (const float*)d_in[8];  // bk cancels in softmax
    const float* Wv = (const float*)d_in[10]; const float* bv = (const float*)d_in[11];
    const float* Wo = (const float*)d_in[12]; const float* bo = (const float*)d_in[13];
    const float* ln1s = (const float*)d_in[14]; const float* ln1b = (const float*)d_in[15];
    const float *ln2s, *ln2b, *W1, *b1, *W2, *b2;
    if (in_sizes[16] == 256) {
        ln2s = (const float*)d_in[16]; ln2b = (const float*)d_in[17];
        W1   = (const float*)d_in[18]; b1   = (const float*)d_in[19];
        W2   = (const float*)d_in[20]; b2   = (const float*)d_in[21];
    } else {
        W1   = (const float*)d_in[16]; b1   = (const float*)d_in[17];
        W2   = (const float*)d_in[18]; b2   = (const float*)d_in[19];
        ln2s = (const float*)d_in[20]; ln2b = (const float*)d_in[21];
    }

    float *p_cmb, *p_bqw, *p_qw, *p_ctx, *p_attn, *p_o, *p_x, *p_h, *p_m;
    cudaGetSymbolAddress((void**)&p_cmb, g_cmb);
    cudaGetSymbolAddress((void**)&p_bqw, g_bqw);
    cudaGetSymbolAddress((void**)&p_qw, g_qw);
    cudaGetSymbolAddress((void**)&p_ctx, g_ctx);
    cudaGetSymbolAddress((void**)&p_attn, g_attn);
    cudaGetSymbolAddress((void**)&p_o, g_o);
    cudaGetSymbolAddress((void**)&p_x, g_x);
    cudaGetSymbolAddress((void**)&p_h, g_h);
    cudaGetSymbolAddress((void**)&p_m, g_m);

    // 1) offsets
    offs_kernel<<<NPIX / 8, 256>>>(hs, W_off, b_off);
    // 2) combined score weights
    prep_cmb<<<1024, 256>>>(Wq, Wk);
    prep_bqw<<<4, 256>>>(bq, Wk);
    // 3) qw = hs @ Cmb + bqw                         [8192 x 1024], K=256
    gemm_big<128, 0><<<dim3(64, 8), 256>>>(hs, DD, 0, p_cmb, 1024, p_bqw, p_qw, 1024, DD);
    // 4) gather + softmax + ctx
    gather_attn<<<NPIX, 256>>>(emb, W_kvp, b_kvp);
    // 5) attn = ctx (block-diag) @ Wv + bv           [8192 x 256], K=256 per head
    gemm_big<64, 0><<<dim3(64, 4), 256>>>(p_ctx, 1024, 256, Wv, DD, bv, p_attn, DD, DD);
    // 6) o = attn @ Wo + bo                          [8192 x 256], K=256
    gemm_big<128, 0><<<dim3(64, 2), 256>>>(p_attn, DD, 0, Wo, DD, bo, p_o, DD, DD);
    // 7) x = LN1(o + hs)
    ln_kernel<<<NPIX, 256>>>(p_o, hs, ln1s, ln1b, p_x);
    // 8) h = gelu(x @ W1 + b1)                       [8192 x 1024], K=256
    gemm_big<128, 1><<<dim3(64, 8), 256>>>(p_x, DD, 0, W1, MLPH, b1, p_h, MLPH, DD);
    // 9) m = h @ W2 + b2                             [8192 x 256], K=1024
    gemm_big<128, 0><<<dim3(64, 2), 256>>>(p_h, MLPH, 0, W2, DD, b2, p_m, DD, MLPH);
    // 10) out = LN2(m + x)
    ln_kernel<<<NPIX, 256>>>(p_m, p_x, ln2s, ln2b, (float*)d_out);
}

// round 8
// speedup vs baseline: 1.3851x; 1.2180x over previous
#include <cuda_runtime.h>
#include <math.h>

#define NPIX 8192
#define DD 256
#define SS 16
#define MLPH 1024

// ---------- scratch ----------
__device__ float g_off[NPIX * 32];
__device__ float g_cmb[DD * 1024];
__device__ float g_bqw[1024];
__device__ float g_qw[(size_t)NPIX * 1024];
__device__ float g_ctx[(size_t)NPIX * 1024];
__device__ float g_attn[(size_t)NPIX * DD];
__device__ float g_o[(size_t)NPIX * DD];
__device__ float g_x[(size_t)NPIX * DD];
__device__ float g_h[(size_t)NPIX * MLPH];
__device__ float g_m[(size_t)NPIX * DD];

__device__ __forceinline__ float gelu_tanh(float v) {
    float c = 0.7978845608028654f * (v + 0.044715f * v * v * v);
    return 0.5f * v * (1.0f + tanhf(c));
}

__device__ __forceinline__ unsigned f2tf(float f) {
    unsigned u;
    asm("cvt.rna.tf32.f32 %0, %1;" : "=r"(u) : "f"(f));
    return u;
}

__device__ __forceinline__ void mma_tf32(float* c, const unsigned* a, const unsigned* b) {
    asm volatile(
        "mma.sync.aligned.m16n8k8.row.col.f32.tf32.tf32.f32 "
        "{%0,%1,%2,%3}, {%4,%5,%6,%7}, {%8,%9}, {%0,%1,%2,%3};"
        : "+f"(c[0]), "+f"(c[1]), "+f"(c[2]), "+f"(c[3])
        : "r"(a[0]), "r"(a[1]), "r"(a[2]), "r"(a[3]), "r"(b[0]), "r"(b[1]));
}

// ---------- 1) offsets ----------
__global__ __launch_bounds__(256) void offs_kernel(
    const float* __restrict__ hs, const float* __restrict__ W_off,
    const float* __restrict__ b_off)
{
    int w = threadIdx.x >> 5, lane = threadIdx.x & 31;
    int p = blockIdx.x * 8 + w;
    const float* hp = hs + (size_t)p * DD;
    float acc = 0.f;
    for (int db = 0; db < DD; db += 32) {
        float hv = hp[db + lane];
        #pragma unroll
        for (int j = 0; j < 32; ++j) {
            float h = __shfl_sync(0xffffffffu, hv, j);
            acc += h * W_off[(db + j) * 32 + lane];
        }
    }
    float z = acc + b_off[lane];
    g_off[p * 32 + lane] = 60.0f / (1.0f + expf(-z)) - 30.0f;
}

// ---------- 2) Cmb / bqw ----------
__global__ __launch_bounds__(256) void prep_cmb(
    const float* __restrict__ Wq, const float* __restrict__ Wk)
{
    int j = blockIdx.x;
    int a = j >> 8, d = j & 255;
    __shared__ float wk_s[64];
    int t = threadIdx.x;
    if (t < 64) wk_s[t] = 0.125f * Wk[d * DD + a * 64 + t];
    __syncthreads();
    const float* wq = Wq + t * DD + a * 64;
    float acc = 0.f;
    #pragma unroll 16
    for (int e = 0; e < 64; ++e) acc += wq[e] * wk_s[e];
    g_cmb[t * 1024 + j] = acc;
}

__global__ void prep_bqw(const float* __restrict__ bq, const float* __restrict__ Wk) {
    int j = blockIdx.x * 256 + threadIdx.x;
    int a = j >> 8, d = j & 255;
    float acc = 0.f;
    #pragma unroll 16
    for (int e = 0; e < 64; ++e)
        acc += bq[a * 64 + e] * 0.125f * Wk[d * DD + a * 64 + e];
    g_bqw[j] = acc;
}

// ---------- tf32 tensor-core GEMM: tile 128x64x32, 8 warps (4x2), warp 32x32 ----------
template <int MODE>
__global__ __launch_bounds__(256) void gemm_tf32(
    const float* __restrict__ A, int lda,
    const float* __restrict__ B, int ldb,
    const float* __restrict__ bias,
    float* __restrict__ C, int ldc, int K)
{
    __shared__ __align__(16) unsigned As[128][36];   // [m][k], stride 36 -> conflict-free quads
    __shared__ __align__(16) unsigned Bs[32][72];    // [k][n], stride 72 -> conflict-free quads

    int t = threadIdx.x;
    int warp = t >> 5, lane = t & 31;
    int wm = warp & 3, wn = warp >> 2;
    int mb = blockIdx.x, nb = blockIdx.y;
    const float* Ab = A + (size_t)(mb * 128) * lda;
    const float* Bb = B + nb * 64;

    int ar = t >> 1, ac = (t & 1) * 16;   // A loader: row ar, k = ac..ac+15
    int br = t >> 3, bc = (t & 7) * 8;    // B loader: k = br, n = bc..bc+7

    float acc[2][4][4];
    #pragma unroll
    for (int mi = 0; mi < 2; ++mi)
        #pragma unroll
        for (int ni = 0; ni < 4; ++ni)
            #pragma unroll
            for (int j = 0; j < 4; ++j) acc[mi][ni][j] = 0.f;

    float4 av[4], bv[2];
    #pragma unroll
    for (int j = 0; j < 4; ++j)
        av[j] = *(const float4*)&Ab[(size_t)ar * lda + ac + j * 4];
    bv[0] = *(const float4*)&Bb[(size_t)br * ldb + bc];
    bv[1] = *(const float4*)&Bb[(size_t)br * ldb + bc + 4];

    int r = lane >> 2, cq = lane & 3;

    for (int k0 = 0; k0 < K; k0 += 32) {
        __syncthreads();
        #pragma unroll
        for (int j = 0; j < 4; ++j) {
            uint4 u = make_uint4(f2tf(av[j].x), f2tf(av[j].y), f2tf(av[j].z), f2tf(av[j].w));
            *(uint4*)&As[ar][ac + j * 4] = u;
        }
        {
            uint4 u0 = make_uint4(f2tf(bv[0].x), f2tf(bv[0].y), f2tf(bv[0].z), f2tf(bv[0].w));
            uint4 u1 = make_uint4(f2tf(bv[1].x), f2tf(bv[1].y), f2tf(bv[1].z), f2tf(bv[1].w));
            *(uint4*)&Bs[br][bc] = u0;
            *(uint4*)&Bs[br][bc + 4] = u1;
        }
        __syncthreads();

        if (k0 + 32 < K) {
            #pragma unroll
            for (int j = 0; j < 4; ++j)
                av[j] = *(const float4*)&Ab[(size_t)ar * lda + k0 + 32 + ac + j * 4];
            bv[0] = *(const float4*)&Bb[(size_t)(k0 + 32 + br) * ldb + bc];
            bv[1] = *(const float4*)&Bb[(size_t)(k0 + 32 + br) * ldb + bc + 4];
        }

        #pragma unroll
        for (int ki = 0; ki < 4; ++ki) {
            int kk = ki * 8;
            unsigned af[2][4], bf[4][2];
            #pragma unroll
            for (int mi = 0; mi < 2; ++mi) {
                int m0 = wm * 32 + mi * 16;
                af[mi][0] = As[m0 + r][kk + cq];
                af[mi][1] = As[m0 + r + 8][kk + cq];
                af[mi][2] = As[m0 + r][kk + cq + 4];
                af[mi][3] = As[m0 + r + 8][kk + cq + 4];
            }
            #pragma unroll
            for (int ni = 0; ni < 4; ++ni) {
                int n0 = wn * 32 + ni * 8;
                bf[ni][0] = Bs[kk + cq][n0 + r];
                bf[ni][1] = Bs[kk + cq + 4][n0 + r];
            }
            #pragma unroll
            for (int mi = 0; mi < 2; ++mi)
                #pragma unroll
                for (int ni = 0; ni < 4; ++ni)
                    mma_tf32(acc[mi][ni], af[mi], bf[ni]);
        }
    }

    // epilogue
    #pragma unroll
    for (int mi = 0; mi < 2; ++mi) {
        int row = mb * 128 + wm * 32 + mi * 16 + r;
        #pragma unroll
        for (int ni = 0; ni < 4; ++ni) {
            int col = nb * 64 + wn * 32 + ni * 8 + 2 * cq;
            float b0 = bias[col], b1 = bias[col + 1];
            float v0 = acc[mi][ni][0] + b0, v1 = acc[mi][ni][1] + b1;
            float v2 = acc[mi][ni][2] + b0, v3 = acc[mi][ni][3] + b1;
            if (MODE == 1) {
                v0 = gelu_tanh(v0); v1 = gelu_tanh(v1);
                v2 = gelu_tanh(v2); v3 = gelu_tanh(v3);
            }
            *(float2*)&C[(size_t)row * ldc + col] = make_float2(v0, v1);
            *(float2*)&C[(size_t)(row + 8) * ldc + col] = make_float2(v2, v3);
        }
    }
}

// ---------- fp32 SIMT GEMM (small: AV block-diag, O) ----------
template <int NTILE, int MODE>
__global__ __launch_bounds__(256) void gemm_big(
    const float* __restrict__ A, int lda, int a_koff,
    const float* __restrict__ B, int ldb,
    const float* __restrict__ bias,
    float* __restrict__ C, int ldc, int K)
{
    constexpr int NR = NTILE / 16;
    __shared__ __align__(16) float As[16][132];
    __shared__ __align__(16) float Bs[16][NTILE + 4];

    int t = threadIdx.x;
    int mb = blockIdx.x, nb = blockIdx.y;
    const float* Ab = A + (size_t)(mb * 128) * lda + nb * a_koff;
    const float* Bb = B + nb * NTILE;

    int am = t >> 2, ak = (t & 3) * 4;
    int bk, bn;
    if (NTILE == 128) { bk = t >> 5; bn = (t & 31) * 4; }
    else              { bk = t >> 4; bn = (t & 15) * 4; }

    int tx = t & 15, ty = t >> 4;
    int m0 = ty * 4, n0 = tx * 4;

    float acc[8][NR];
    #pragma unroll
    for (int i = 0; i < 8; ++i)
        #pragma unroll
        for (int j = 0; j < NR; ++j) acc[i][j] = 0.f;

    float4 a0p = *(const float4*)&Ab[(size_t)am * lda + ak];
    float4 a1p = *(const float4*)&Ab[(size_t)(am + 64) * lda + ak];
    float4 b0p = *(const float4*)&Bb[(size_t)bk * ldb + bn];
    float4 b1p;
    if (NTILE == 128) b1p = *(const float4*)&Bb[(size_t)(bk + 8) * ldb + bn];

    for (int k0 = 0; k0 < K; k0 += 16) {
        __syncthreads();
        As[ak + 0][am] = a0p.x; As[ak + 1][am] = a0p.y;
        As[ak + 2][am] = a0p.z; As[ak + 3][am] = a0p.w;
        As[ak + 0][am + 64] = a1p.x; As[ak + 1][am + 64] = a1p.y;
        As[ak + 2][am + 64] = a1p.z; As[ak + 3][am + 64] = a1p.w;
        *(float4*)&Bs[bk][bn] = b0p;
        if (NTILE == 128) *(float4*)&Bs[bk + 8][bn] = b1p;
        __syncthreads();

        if (k0 + 16 < K) {
            a0p = *(const float4*)&Ab[(size_t)am * lda + k0 + 16 + ak];
            a1p = *(const float4*)&Ab[(size_t)(am + 64) * lda + k0 + 16 + ak];
            b0p = *(const float4*)&Bb[(size_t)(k0 + 16 + bk) * ldb + bn];
            if (NTILE == 128) b1p = *(const float4*)&Bb[(size_t)(k0 + 24 + bk) * ldb + bn];
        }

        #pragma unroll
        for (int k = 0; k < 16; ++k) {
            float4 av0 = *(const float4*)&As[k][m0];
            float4 av1 = *(const float4*)&As[k][m0 + 64];
            float ar[8] = {av0.x, av0.y, av0.z, av0.w, av1.x, av1.y, av1.z, av1.w};
            float br[NR];
            float4 bv0 = *(const float4*)&Bs[k][n0];
            br[0] = bv0.x; br[1] = bv0.y; br[2] = bv0.z; br[3] = bv0.w;
            if (NTILE == 128) {
                float4 bv1 = *(const float4*)&Bs[k][n0 + 64];
                br[4] = bv1.x; br[5] = bv1.y; br[6] = bv1.z; br[7] = bv1.w;
            }
            #pragma unroll
            for (int i = 0; i < 8; ++i)
                #pragma unroll
                for (int j = 0; j < NR; ++j)
                    acc[i][j] += ar[i] * br[j];
        }
    }

    float4 bb0 = *(const float4*)&bias[nb * NTILE + n0];
    float4 bb1;
    if (NTILE == 128) bb1 = *(const float4*)&bias[nb * NTILE + n0 + 64];
    #pragma unroll
    for (int i = 0; i < 8; ++i) {
        int row = mb * 128 + (i < 4 ? m0 + i : m0 + 60 + i);
        float4 c0;
        c0.x = acc[i][0] + bb0.x; c0.y = acc[i][1] + bb0.y;
        c0.z = acc[i][2] + bb0.z; c0.w = acc[i][3] + bb0.w;
        if (MODE == 1) {
            c0.x = gelu_tanh(c0.x); c0.y = gelu_tanh(c0.y);
            c0.z = gelu_tanh(c0.z); c0.w = gelu_tanh(c0.w);
        }
        *(float4*)&C[(size_t)row * ldc + nb * NTILE + n0] = c0;
        if (NTILE == 128) {
            float4 c1;
            c1.x = acc[i][4] + bb1.x; c1.y = acc[i][5] + bb1.y;
            c1.z = acc[i][6] + bb1.z; c1.w = acc[i][7] + bb1.w;
            if (MODE == 1) {
                c1.x = gelu_tanh(c1.x); c1.y = gelu_tanh(c1.y);
                c1.z = gelu_tanh(c1.z); c1.w = gelu_tanh(c1.w);
            }
            *(float4*)&C[(size_t)row * ldc + nb * NTILE + n0 + 64] = c1;
        }
    }
}

// ---------- gather + scores + softmax + ctx ----------
__global__ __launch_bounds__(256) void gather_attn(
    const float* __restrict__ emb,
    const float* __restrict__ W_kvp, const float* __restrict__ b_kvp)
{
    __shared__ __align__(16) float kvs[SS][264];
    __shared__ __align__(16) float qws[1024];
    __shared__ float offs[32];
    __shared__ float scs[64];
    __shared__ float ps[64];

    int t = threadIdx.x, p = blockIdx.x;
    int n = p >> 12, hh = (p >> 6) & 63, ww = p & 63;

    if (t < 32) offs[t] = g_off[p * 32 + t];
    *(float4*)&qws[t * 4] = *(const float4*)&g_qw[(size_t)p * 1024 + t * 4];
    __syncthreads();

    {
        float wk0 = W_kvp[t], wk1 = W_kvp[DD + t], bkv = b_kvp[t];
        const float* base = emb + (size_t)n * 64 * 64 * DD + t;
        float fh = (float)hh, fw = (float)ww;
        #pragma unroll 4
        for (int s = 0; s < SS; ++s) {
            float oy = offs[2 * s], ox = offs[2 * s + 1];
            float y = fminf(fmaxf(fh + oy, 0.f), 63.f);
            float x = fminf(fmaxf(fw + ox, 0.f), 63.f);
            float y0f = floorf(y), x0f = floorf(x);
            float wy = y - y0f, wx = x - x0f;
            int y0 = (int)y0f, x0 = (int)x0f;
            int y1 = min(y0 + 1, 63), x1 = min(x0 + 1, 63);
            float v00 = base[(y0 * 64 + x0) * DD];
            float v01 = base[(y0 * 64 + x1) * DD];
            float v10 = base[(y1 * 64 + x0) * DD];
            float v11 = base[(y1 * 64 + x1) * DD];
            float val = (1.f - wy) * ((1.f - wx) * v00 + wx * v01)
                      +        wy  * ((1.f - wx) * v10 + wx * v11);
            kvs[s][t] = val + oy * wk0 + ox * wk1 + bkv;
        }
    }
    __syncthreads();

    {
        int as = t >> 2, c = t & 3;
        int a = as >> 4, s = as & 15;
        const float* kp = &kvs[s][c * 64];
        const float* qp = &qws[a * 256 + c * 64];
        float acc = 0.f;
        #pragma unroll 8
        for (int i = 0; i < 64; i += 4) {
            float4 k4 = *(const float4*)&kp[i];
            float4 q4 = *(const float4*)&qp[i];
            acc += k4.x * q4.x + k4.y * q4.y + k4.z * q4.z + k4.w * q4.w;
        }
        acc += __shfl_xor_sync(0xffffffffu, acc, 1);
        acc += __shfl_xor_sync(0xffffffffu, acc, 2);
        if (c == 0) scs[as] = acc;
    }
    __syncthreads();

    if (t < 64) {
        float sc = scs[t];
        float mx = sc;
        #pragma unroll
        for (int m = 8; m >= 1; m >>= 1)
            mx = fmaxf(mx, __shfl_xor_sync(0xffffffffu, mx, m, 16));
        float ex = expf(sc - mx);
        float sum = ex;
        #pragma unroll
        for (int m = 8; m >= 1; m >>= 1)
            sum += __shfl_xor_sync(0xffffffffu, sum, m, 16);
        ps[t] = ex / sum;
    }
    __syncthreads();

    {
        float kcol[SS];
        #pragma unroll
        for (int s = 0; s < SS; ++s) kcol[s] = kvs[s][t];
        #pragma unroll
        for (int a = 0; a < 4; ++a) {
            float acc = 0.f;
            #pragma unroll
            for (int s = 0; s < SS; ++s) acc += ps[a * 16 + s] * kcol[s];
            g_ctx[(size_t)p * 1024 + a * 256 + t] = acc;
        }
    }
}

// ---------- layernorm ----------
__global__ __launch_bounds__(256) void ln_kernel(
    const float* __restrict__ g, const float* __restrict__ res,
    const float* __restrict__ s, const float* __restrict__ b,
    float* __restrict__ out)
{
    __shared__ float red[16];
    int r = blockIdx.x, t = threadIdx.x;
    float v = g[(size_t)r * DD + t] + res[(size_t)r * DD + t];
    float s1 = v, s2 = v * v;
    #pragma unroll
    for (int m = 16; m >= 1; m >>= 1) {
        s1 += __shfl_xor_sync(0xffffffffu, s1, m);
        s2 += __shfl_xor_sync(0xffffffffu, s2, m);
    }
    int wid = t >> 5, lid = t & 31;
    if (lid == 0) { red[wid] = s1; red[8 + wid] = s2; }
    __syncthreads();
    float m1 = 0.f, m2 = 0.f;
    #pragma unroll
    for (int w = 0; w < 8; ++w) { m1 += red[w]; m2 += red[8 + w]; }
    m1 *= (1.f / 256.f);
    m2 = m2 * (1.f / 256.f) - m1 * m1;
    out[(size_t)r * DD + t] = (v - m1) * rsqrtf(m2 + 1e-6f) * s[t] + b[t];
}

// ---------- launcher ----------
extern "C" void kernel_launch(void* const* d_in, const int* in_sizes, int n_in,
                              void* d_out, int out_size)
{
    const float* hs    = (const float*)d_in[0];
    const float* emb   = (const float*)d_in[1];
    const float* W_off = (const float*)d_in[2];
    const float* b_off = (const float*)d_in[3];
    const float* W_kvp = (const float*)d_in[4];
    const float* b_kvp = (const float*)d_in[5];
    const float* Wq = (const float*)d_in[6];  const float* bq = (const float*)d_in[7];
    const float* Wk = (const float*)d_in[8];
    const float* Wv = (const float*)d_in[10]; const float* bv = (const float*)d_in[11];
    const float* Wo = (const float*)d_in[12]; const float* bo = (const float*)d_in[13];
    const float* ln1s = (const float*)d_in[14]; const float* ln1b = (const float*)d_in[15];
    const float *ln2s, *ln2b, *W1, *b1, *W2, *b2;
    if (in_sizes[16] == 256) {
        ln2s = (const float*)d_in[16]; ln2b = (const float*)d_in[17];
        W1   = (const float*)d_in[18]; b1   = (const float*)d_in[19];
        W2   = (const float*)d_in[20]; b2   = (const float*)d_in[21];
    } else {
        W1   = (const float*)d_in[16]; b1   = (const float*)d_in[17];
        W2   = (const float*)d_in[18]; b2   = (const float*)d_in[19];
        ln2s = (const float*)d_in[20]; ln2b = (const float*)d_in[21];
    }

    float *p_cmb, *p_bqw, *p_qw, *p_ctx, *p_attn, *p_o, *p_x, *p_h, *p_m;
    cudaGetSymbolAddress((void**)&p_cmb, g_cmb);
    cudaGetSymbolAddress((void**)&p_bqw, g_bqw);
    cudaGetSymbolAddress((void**)&p_qw, g_qw);
    cudaGetSymbolAddress((void**)&p_ctx, g_ctx);
    cudaGetSymbolAddress((void**)&p_attn, g_attn);
    cudaGetSymbolAddress((void**)&p_o, g_o);
    cudaGetSymbolAddress((void**)&p_x, g_x);
    cudaGetSymbolAddress((void**)&p_h, g_h);
    cudaGetSymbolAddress((void**)&p_m, g_m);

    // 1) offsets
    offs_kernel<<<NPIX / 8, 256>>>(hs, W_off, b_off);
    // 2) combined score weights
    prep_cmb<<<1024, 256>>>(Wq, Wk);
    prep_bqw<<<4, 256>>>(bq, Wk);
    // 3) qw = hs @ Cmb + bqw        [8192 x 1024], K=256  (tf32 TC)
    gemm_tf32<0><<<dim3(64, 16), 256>>>(hs, DD, p_cmb, 1024, p_bqw, p_qw, 1024, DD);
    // 4) gather + softmax + ctx
    gather_attn<<<NPIX, 256>>>(emb, W_kvp, b_kvp);
    // 5) attn = ctx (block-diag) @ Wv + bv   [8192 x 256] (fp32 SIMT)
    gemm_big<64, 0><<<dim3(64, 4), 256>>>(p_ctx, 1024, 256, Wv, DD, bv, p_attn, DD, DD);
    // 6) o = attn @ Wo + bo         [8192 x 256] (fp32 SIMT, 256 CTAs)
    gemm_big<64, 0><<<dim3(64, 4), 256>>>(p_attn, DD, 0, Wo, DD, bo, p_o, DD, DD);
    // 7) x = LN1(o + hs)
    ln_kernel<<<NPIX, 256>>>(p_o, hs, ln1s, ln1b, p_x);
    // 8) h = gelu(x @ W1 + b1)      [8192 x 1024], K=256  (tf32 TC)
    gemm_tf32<1><<<dim3(64, 16), 256>>>(p_x, DD, W1, MLPH, b1, p_h, MLPH, DD);
    // 9) m = h @ W2 + b2            [8192 x 256], K=1024  (tf32 TC)
    gemm_tf32<0><<<dim3(64, 4), 256>>>(p_h, MLPH, W2, DD, b2, p_m, DD, MLPH);
    // 10) out = LN2(m + x)
    ln_kernel<<<NPIX, 256>>>(p_m, p_x, ln2s, ln2b, (float*)d_out);
}